// round 14
// baseline (speedup 1.0000x reference)
#include <cuda_runtime.h>
#include <cuda_bf16.h>

#define T_SEQ 4096
#define B_SZ  4
#define D_IN  1024
#define P_DIM 64
#define M_ROWS (B_SZ * T_SEQ)   // 16384
#define NSPLIT 2

// qkv scratch: [head (q/k/v)][m = b*T + t][p]
__device__ __align__(16) float g_qkv[3u * M_ROWS * P_DIM];
// split partials: unnormalized O, and (m, l) per row per split
__device__ __align__(16) float g_po[NSPLIT * M_ROWS * P_DIM];
__device__ __align__(16) float g_pml[NSPLIT * M_ROWS * 2];

// ---------------------------------------------------------------------------
// tf32 helpers
// ---------------------------------------------------------------------------
__device__ __forceinline__ unsigned f2tf(float f) {
    unsigned u;
    asm("cvt.rna.tf32.f32 %0, %1;" : "=r"(u) : "f"(f));
    return u;
}

__device__ __forceinline__ void mma_tf32(float* d, const unsigned* a, const unsigned* b) {
    asm volatile(
        "mma.sync.aligned.m16n8k8.row.col.f32.tf32.tf32.f32 "
        "{%0,%1,%2,%3}, {%4,%5,%6,%7}, {%8,%9}, {%0,%1,%2,%3};"
        : "+f"(d[0]), "+f"(d[1]), "+f"(d[2]), "+f"(d[3])
        : "r"(a[0]), "r"(a[1]), "r"(a[2]), "r"(a[3]),
          "r"(b[0]), "r"(b[1]));
}

// split f into tf32 hi + tf32 lo (lo = tf32(f - float(hi)))
__device__ __forceinline__ void f2tf_split(float f, unsigned& hi, unsigned& lo) {
    hi = f2tf(f);
    float r = f - __uint_as_float(hi);
    lo = f2tf(r);
}

// ---------------------------------------------------------------------------
// QKV projection with split-tf32 (3xTF32) tensor cores: near-fp32 accuracy.
// Block tile: 128(M) x 64(N per head), k-tile 64, 256 threads = 8 warps.
// Warp grid 4(M) x 2(N): each warp owns 32x32 = 2 m16 x 4 n8 fragments.
// Per k8 step: D += Ah*Bh + Al*Bh + Ah*Bl  (Al*Bl dropped, ~2^-22).
// A smem stride 68, B stride 72 (hi and lo tiles each): conflict-free phases.
// ---------------------------------------------------------------------------
#define AS_STRIDE 68
#define BS_STRIDE 72
#define GEMM_SMEM ((2 * 128 * AS_STRIDE + 2 * 64 * BS_STRIDE) * 4)  // 106496 B

__global__ __launch_bounds__(256) void qkv_gemm_kernel(
    const float* __restrict__ x,
    const float* __restrict__ W,
    const float* __restrict__ bias)
{
    extern __shared__ unsigned sm_u[];
    unsigned* Ah = sm_u;                        // [128][68]
    unsigned* Al = Ah + 128 * AS_STRIDE;        // [128][68]
    unsigned* Bh = Al + 128 * AS_STRIDE;        // [64][72]
    unsigned* Bl = Bh + 64 * BS_STRIDE;         // [64][72]

    const int tid  = threadIdx.x;
    const int m0   = blockIdx.x * 128;
    const int head = blockIdx.y;
    const int n0   = head * 64;
    const int warp = tid >> 5;
    const int lane = tid & 31;
    const int wm   = warp & 3;     // m offset wm*32
    const int wn   = warp >> 2;    // n offset wn*32
    const int gid  = lane >> 2;    // 0..7
    const int lid4 = lane & 3;     // 0..3

    float d[2][4][4];
#pragma unroll
    for (int mi = 0; mi < 2; mi++)
#pragma unroll
        for (int ni = 0; ni < 4; ni++)
#pragma unroll
            for (int r = 0; r < 4; r++) d[mi][ni][r] = 0.f;

    for (int k0 = 0; k0 < D_IN; k0 += 64) {
        // A tile: 128 rows x 64 k, 8 f4 per thread, coalesced
#pragma unroll
        for (int it = 0; it < 8; it++) {
            int s   = tid + it * 256;
            int row = s >> 4;
            int c   = s & 15;
            float4 v = *(const float4*)&x[(size_t)(m0 + row) * D_IN + k0 + c * 4];
            uint4 uh, ul;
            f2tf_split(v.x, uh.x, ul.x);
            f2tf_split(v.y, uh.y, ul.y);
            f2tf_split(v.z, uh.z, ul.z);
            f2tf_split(v.w, uh.w, ul.w);
            *(uint4*)&Ah[row * AS_STRIDE + c * 4] = uh;
            *(uint4*)&Al[row * AS_STRIDE + c * 4] = ul;
        }
        // B tile: 64 k-rows x 64 n, 4 f4 per thread
#pragma unroll
        for (int it = 0; it < 4; it++) {
            int s  = tid + it * 256;
            int kk = s >> 4;
            int c  = s & 15;
            float4 v = *(const float4*)&W[(size_t)(k0 + kk) * 192 + n0 + c * 4];
            uint4 uh, ul;
            f2tf_split(v.x, uh.x, ul.x);
            f2tf_split(v.y, uh.y, ul.y);
            f2tf_split(v.z, uh.z, ul.z);
            f2tf_split(v.w, uh.w, ul.w);
            *(uint4*)&Bh[kk * BS_STRIDE + c * 4] = uh;
            *(uint4*)&Bl[kk * BS_STRIDE + c * 4] = ul;
        }
        __syncthreads();

#pragma unroll
        for (int k8 = 0; k8 < 8; k8++) {
            unsigned ah[2][4], al[2][4], bh[4][2], bl[4][2];
#pragma unroll
            for (int mi = 0; mi < 2; mi++) {
                int rb = wm * 32 + mi * 16;
                int o00 = (rb + gid    ) * AS_STRIDE + k8 * 8 + lid4;
                int o10 = (rb + gid + 8) * AS_STRIDE + k8 * 8 + lid4;
                ah[mi][0] = Ah[o00];     ah[mi][1] = Ah[o10];
                ah[mi][2] = Ah[o00 + 4]; ah[mi][3] = Ah[o10 + 4];
                al[mi][0] = Al[o00];     al[mi][1] = Al[o10];
                al[mi][2] = Al[o00 + 4]; al[mi][3] = Al[o10 + 4];
            }
#pragma unroll
            for (int ni = 0; ni < 4; ni++) {
                int nb = wn * 32 + ni * 8;
                int o0 = (k8 * 8 + lid4    ) * BS_STRIDE + nb + gid;
                int o1 = (k8 * 8 + lid4 + 4) * BS_STRIDE + nb + gid;
                bh[ni][0] = Bh[o0]; bh[ni][1] = Bh[o1];
                bl[ni][0] = Bl[o0]; bl[ni][1] = Bl[o1];
            }
#pragma unroll
            for (int mi = 0; mi < 2; mi++)
#pragma unroll
                for (int ni = 0; ni < 4; ni++) {
                    mma_tf32(d[mi][ni], ah[mi], bh[ni]);
                    mma_tf32(d[mi][ni], al[mi], bh[ni]);
                    mma_tf32(d[mi][ni], ah[mi], bl[ni]);
                }
        }
        __syncthreads();
    }

    // epilogue: bias add, store fragments to g_qkv[head]
    float* outp = g_qkv + (size_t)head * M_ROWS * P_DIM;
#pragma unroll
    for (int mi = 0; mi < 2; mi++) {
        int row = m0 + wm * 32 + mi * 16 + gid;
#pragma unroll
        for (int ni = 0; ni < 4; ni++) {
            int col = wn * 32 + ni * 8 + 2 * lid4;
            float b0 = bias[n0 + col];
            float b1 = bias[n0 + col + 1];
            float2 v0 = make_float2(d[mi][ni][0] + b0, d[mi][ni][1] + b1);
            float2 v1 = make_float2(d[mi][ni][2] + b0, d[mi][ni][3] + b1);
            *(float2*)&outp[(size_t)row * P_DIM + col]       = v0;
            *(float2*)&outp[(size_t)(row + 8) * P_DIM + col] = v1;
        }
    }
}

// ---------------------------------------------------------------------------
// Flash-style causal attention, register-blocked + key-split (unchanged).
// ---------------------------------------------------------------------------
__global__ __launch_bounds__(128) void attn_kernel()
{
    extern __shared__ float sm[];
    float* Qs = sm;                 // [64][68]
    float* Ks = sm + 4352;          // [64][68]
    float* Vs = sm + 8704;          // [64][68]
    float* Ps = sm + 13056;         // [64][68]

    const int b    = blockIdx.y;
    const int qt   = (int)gridDim.x - 1 - (int)blockIdx.x;  // heavy blocks first
    const int sp   = blockIdx.z;
    const int tid  = threadIdx.x;
    const int rowg = tid >> 4;      // 0..7
    const int keyg = tid & 15;      // 0..15
    const int r0   = rowg * 8;

    const int n   = qt + 1;
    const int kt0 = sp * n / NSPLIT;
    const int kt1 = (sp + 1) * n / NSPLIT;

    const float* qg = g_qkv;
    const float* kg = g_qkv + (size_t)M_ROWS * P_DIM;
    const float* vg = g_qkv + (size_t)2 * M_ROWS * P_DIM;

    const int qrow0 = b * T_SEQ + qt * 64;

#pragma unroll
    for (int it = 0; it < 8; it++) {
        int s   = tid + it * 128;
        int row = s >> 4;
        int c   = s & 15;
        *(float4*)&Qs[row * 68 + c * 4] =
            *(const float4*)&qg[(size_t)(qrow0 + row) * P_DIM + c * 4];
    }

    float o[8][4], m[8], l[8];
#pragma unroll
    for (int i = 0; i < 8; i++) {
        m[i] = -1e30f; l[i] = 0.f;
        o[i][0] = o[i][1] = o[i][2] = o[i][3] = 0.f;
    }

    for (int kt = kt0; kt < kt1; kt++) {
        __syncthreads();
        const int krow0 = b * T_SEQ + kt * 64;
#pragma unroll
        for (int it = 0; it < 8; it++) {
            int s   = tid + it * 128;
            int row = s >> 4;
            int c   = s & 15;
            *(float4*)&Ks[row * 68 + c * 4] =
                *(const float4*)&kg[(size_t)(krow0 + row) * P_DIM + c * 4];
            *(float4*)&Vs[row * 68 + c * 4] =
                *(const float4*)&vg[(size_t)(krow0 + row) * P_DIM + c * 4];
        }
        __syncthreads();

        float sv[8][4];
#pragma unroll
        for (int i = 0; i < 8; i++)
            sv[i][0] = sv[i][1] = sv[i][2] = sv[i][3] = 0.f;

#pragma unroll
        for (int p4 = 0; p4 < 16; p4++) {
            float4 kv[4];
#pragma unroll
            for (int j = 0; j < 4; j++)
                kv[j] = *(float4*)&Ks[(keyg + 16 * j) * 68 + p4 * 4];
#pragma unroll
            for (int i = 0; i < 8; i++) {
                float4 q4 = *(float4*)&Qs[(r0 + i) * 68 + p4 * 4];
#pragma unroll
                for (int j = 0; j < 4; j++) {
                    sv[i][j] += q4.x * kv[j].x;
                    sv[i][j] += q4.y * kv[j].y;
                    sv[i][j] += q4.z * kv[j].z;
                    sv[i][j] += q4.w * kv[j].w;
                }
            }
        }

        if (kt == qt) {
#pragma unroll
            for (int i = 0; i < 8; i++) {
                int rl = r0 + i;
#pragma unroll
                for (int j = 0; j < 4; j++)
                    if (keyg + 16 * j > rl) sv[i][j] = -1e30f;
            }
        }

#pragma unroll
        for (int i = 0; i < 8; i++) {
            float tmax = fmaxf(fmaxf(sv[i][0], sv[i][1]), fmaxf(sv[i][2], sv[i][3]));
            tmax = fmaxf(tmax, __shfl_xor_sync(0xffffffffu, tmax, 1));
            tmax = fmaxf(tmax, __shfl_xor_sync(0xffffffffu, tmax, 2));
            tmax = fmaxf(tmax, __shfl_xor_sync(0xffffffffu, tmax, 4));
            tmax = fmaxf(tmax, __shfl_xor_sync(0xffffffffu, tmax, 8));

            float mnew  = fmaxf(m[i], tmax);
            float scale = __expf(m[i] - mnew);
            float lsum  = 0.f;
#pragma unroll
            for (int j = 0; j < 4; j++) {
                float p = __expf(sv[i][j] - mnew);
                lsum += p;
                Ps[(r0 + i) * 68 + keyg + 16 * j] = p;
            }
            lsum += __shfl_xor_sync(0xffffffffu, lsum, 1);
            lsum += __shfl_xor_sync(0xffffffffu, lsum, 2);
            lsum += __shfl_xor_sync(0xffffffffu, lsum, 4);
            lsum += __shfl_xor_sync(0xffffffffu, lsum, 8);

            l[i] = l[i] * scale + lsum;
            m[i] = mnew;
            o[i][0] *= scale; o[i][1] *= scale; o[i][2] *= scale; o[i][3] *= scale;
        }
        __syncthreads();

#pragma unroll
        for (int j4 = 0; j4 < 16; j4++) {
            float4 v4[4];
#pragma unroll
            for (int j = 0; j < 4; j++)
                v4[j] = *(float4*)&Vs[(j4 * 4 + j) * 68 + keyg * 4];
#pragma unroll
            for (int i = 0; i < 8; i++) {
                float4 p4 = *(float4*)&Ps[(r0 + i) * 68 + j4 * 4];
                o[i][0] += p4.x * v4[0].x; o[i][0] += p4.y * v4[1].x;
                o[i][0] += p4.z * v4[2].x; o[i][0] += p4.w * v4[3].x;
                o[i][1] += p4.x * v4[0].y; o[i][1] += p4.y * v4[1].y;
                o[i][1] += p4.z * v4[2].y; o[i][1] += p4.w * v4[3].y;
                o[i][2] += p4.x * v4[0].z; o[i][2] += p4.y * v4[1].z;
                o[i][2] += p4.z * v4[2].z; o[i][2] += p4.w * v4[3].z;
                o[i][3] += p4.x * v4[0].w; o[i][3] += p4.y * v4[1].w;
                o[i][3] += p4.z * v4[2].w; o[i][3] += p4.w * v4[3].w;
            }
        }
    }

    float* po  = g_po  + (size_t)sp * M_ROWS * P_DIM;
    float* pml = g_pml + (size_t)sp * M_ROWS * 2;
#pragma unroll
    for (int i = 0; i < 8; i++) {
        int row = qrow0 + r0 + i;
        float4 ov;
        ov.x = o[i][0]; ov.y = o[i][1]; ov.z = o[i][2]; ov.w = o[i][3];
        *(float4*)&po[(size_t)row * P_DIM + keyg * 4] = ov;
        if (keyg == 0) {
            pml[row * 2 + 0] = m[i];
            pml[row * 2 + 1] = l[i];
        }
    }
}

// ---------------------------------------------------------------------------
// Combine the NSPLIT partials.
// ---------------------------------------------------------------------------
__global__ __launch_bounds__(256) void combine_kernel(float* __restrict__ out)
{
    int idx = blockIdx.x * 256 + threadIdx.x;
    int row = idx >> 4;
    int c   = idx & 15;

    float m0 = g_pml[row * 2 + 0];
    float l0 = g_pml[row * 2 + 1];
    float m1 = g_pml[(size_t)M_ROWS * 2 + row * 2 + 0];
    float l1 = g_pml[(size_t)M_ROWS * 2 + row * 2 + 1];

    float M  = fmaxf(m0, m1);
    float w0 = __expf(m0 - M);
    float w1 = __expf(m1 - M);
    float inv = 1.0f / (l0 * w0 + l1 * w1);

    float4 a = *(const float4*)&g_po[(size_t)row * P_DIM + c * 4];
    float4 b = *(const float4*)&g_po[(size_t)(M_ROWS + row) * P_DIM + c * 4];
    float4 r;
    r.x = (a.x * w0 + b.x * w1) * inv;
    r.y = (a.y * w0 + b.y * w1) * inv;
    r.z = (a.z * w0 + b.z * w1) * inv;
    r.w = (a.w * w0 + b.w * w1) * inv;
    *(float4*)&out[(size_t)row * P_DIM + c * 4] = r;
}

#define ATTN_SMEM (4 * 64 * 68 * 4)   // 69632 bytes

extern "C" void kernel_launch(void* const* d_in, const int* in_sizes, int n_in,
                              void* d_out, int out_size)
{
    const float* x    = (const float*)d_in[0];   // (4, 4096, 1024)
    const float* W    = (const float*)d_in[1];   // (1024, 192)
    const float* bias = (const float*)d_in[2];   // (192,)
    float* out        = (float*)d_out;           // (4, 4096, 64)

    cudaFuncSetAttribute(qkv_gemm_kernel,
                         cudaFuncAttributeMaxDynamicSharedMemorySize, GEMM_SMEM);
    cudaFuncSetAttribute(attn_kernel,
                         cudaFuncAttributeMaxDynamicSharedMemorySize, ATTN_SMEM);

    qkv_gemm_kernel<<<dim3(M_ROWS / 128, 3), 256, GEMM_SMEM>>>(x, W, bias);
    attn_kernel<<<dim3(T_SEQ / 64, B_SZ, NSPLIT), 128, ATTN_SMEM>>>();
    combine_kernel<<<(M_ROWS * 16) / 256, 256>>>(out);
}

// round 15
// speedup vs baseline: 1.8379x; 1.8379x over previous
#include <cuda_runtime.h>
#include <cuda_bf16.h>

#define T_SEQ 4096
#define B_SZ  4
#define D_IN  1024
#define P_DIM 64
#define M_ROWS (B_SZ * T_SEQ)   // 16384
#define NSPLIT 2

typedef unsigned long long u64;

// qkv scratch: [head (q/k/v)][m = b*T + t][p]
__device__ __align__(16) float g_qkv[3u * M_ROWS * P_DIM];
// split partials: unnormalized O, and (m, l) per row per split
__device__ __align__(16) float g_po[NSPLIT * M_ROWS * P_DIM];
__device__ __align__(16) float g_pml[NSPLIT * M_ROWS * 2];

// ---------------------------------------------------------------------------
// packed f32x2 helpers (sm_103a FFMA2 path — only reachable via PTX)
// ---------------------------------------------------------------------------
__device__ __forceinline__ u64 fma2(u64 a, u64 b, u64 c) {
    u64 d;
    asm("fma.rn.f32x2 %0, %1, %2, %3;" : "=l"(d) : "l"(a), "l"(b), "l"(c));
    return d;
}
__device__ __forceinline__ u64 mul2(u64 a, u64 b) {
    u64 d;
    asm("mul.rn.f32x2 %0, %1, %2;" : "=l"(d) : "l"(a), "l"(b));
    return d;
}
__device__ __forceinline__ u64 pack2(float x, float y) {
    u64 r;
    asm("mov.b64 %0, {%1, %2};" : "=l"(r) : "f"(x), "f"(y));
    return r;
}
__device__ __forceinline__ float2 unpack2(u64 v) {
    float2 r;
    asm("mov.b64 {%0, %1}, %2;" : "=f"(r.x), "=f"(r.y) : "l"(v));
    return r;
}

// ---------------------------------------------------------------------------
// QKV projection: fp32 SIMT (known-good R8 version, 205us).
// Block: 64(M) x 64(N) tile, 256 threads, 4x4 micro-tile, k-tile 32.
// ---------------------------------------------------------------------------
__global__ __launch_bounds__(256) void qkv_gemm_kernel(
    const float* __restrict__ x,
    const float* __restrict__ W,
    const float* __restrict__ bias)
{
    __shared__ float As[32][68];   // [k][m]
    __shared__ float Bs[32][68];   // [k][n]

    const int m0   = blockIdx.x * 64;
    const int head = blockIdx.y;
    const int n0   = head * 64;
    const int tid  = threadIdx.x;
    const int tx   = tid & 15;
    const int ty   = tid >> 4;

    float acc[4][4];
#pragma unroll
    for (int i = 0; i < 4; i++)
#pragma unroll
        for (int j = 0; j < 4; j++) acc[i][j] = 0.f;

    for (int k0 = 0; k0 < D_IN; k0 += 32) {
#pragma unroll
        for (int i = 0; i < 2; i++) {
            int s   = tid + i * 256;
            int row = s >> 3;
            int kc  = s & 7;
            float4 xv = *(const float4*)&x[(size_t)(m0 + row) * D_IN + k0 + kc * 4];
            As[kc * 4 + 0][row] = xv.x;
            As[kc * 4 + 1][row] = xv.y;
            As[kc * 4 + 2][row] = xv.z;
            As[kc * 4 + 3][row] = xv.w;
        }
#pragma unroll
        for (int i = 0; i < 2; i++) {
            int s  = tid + i * 256;
            int kk = s >> 4;
            int nc = s & 15;
            *(float4*)&Bs[kk][nc * 4] =
                *(const float4*)&W[(size_t)(k0 + kk) * 192 + n0 + nc * 4];
        }
        __syncthreads();

#pragma unroll
        for (int kk = 0; kk < 32; kk++) {
            float4 a4 = *(float4*)&As[kk][ty * 4];
            float4 b4 = *(float4*)&Bs[kk][tx * 4];
            float av[4] = {a4.x, a4.y, a4.z, a4.w};
            float bv[4] = {b4.x, b4.y, b4.z, b4.w};
#pragma unroll
            for (int i = 0; i < 4; i++)
#pragma unroll
                for (int j = 0; j < 4; j++)
                    acc[i][j] += av[i] * bv[j];
        }
        __syncthreads();
    }

    float4 bb = *(const float4*)&bias[n0 + tx * 4];
    float bv[4] = {bb.x, bb.y, bb.z, bb.w};
    float* outp = g_qkv + (size_t)head * M_ROWS * P_DIM;
#pragma unroll
    for (int i = 0; i < 4; i++) {
        int m = m0 + ty * 4 + i;
        float4 o;
        o.x = acc[i][0] + bv[0];
        o.y = acc[i][1] + bv[1];
        o.z = acc[i][2] + bv[2];
        o.w = acc[i][3] + bv[3];
        *(float4*)&outp[(size_t)m * P_DIM + tx * 4] = o;
    }
}

// ---------------------------------------------------------------------------
// Flash-style causal attention, register-blocked + key-split + packed FFMA2.
// Block = (query tile qt of 64 rows, batch b, split s). 128 threads:
//   rowg = tid>>4 (8 rows), keyg = tid&15 (4 keys interleaved, 4 out dims).
// S-loop: packed accumulation over p-pairs (acc2 lo/hi summed at the end).
// PV-loop: packed over dim-pairs, P broadcast via mov.b64 {p,p} (alu pipe).
// Post-softmax sync is warp-local (Ps rows 16w..16w+15 stay inside warp w).
// ---------------------------------------------------------------------------
__global__ __launch_bounds__(128) void attn_kernel()
{
    extern __shared__ float sm[];
    float* Qs = sm;                 // [64][68]
    float* Ks = sm + 4352;          // [64][68]
    float* Vs = sm + 8704;          // [64][68]
    float* Ps = sm + 13056;         // [64][68]

    const int b    = blockIdx.y;
    const int qt   = (int)gridDim.x - 1 - (int)blockIdx.x;  // heavy blocks first
    const int sp   = blockIdx.z;
    const int tid  = threadIdx.x;
    const int rowg = tid >> 4;      // 0..7
    const int keyg = tid & 15;      // 0..15
    const int r0   = rowg * 8;

    const int n   = qt + 1;
    const int kt0 = sp * n / NSPLIT;
    const int kt1 = (sp + 1) * n / NSPLIT;

    const float* qg = g_qkv;
    const float* kg = g_qkv + (size_t)M_ROWS * P_DIM;
    const float* vg = g_qkv + (size_t)2 * M_ROWS * P_DIM;

    const int qrow0 = b * T_SEQ + qt * 64;

#pragma unroll
    for (int it = 0; it < 8; it++) {
        int s   = tid + it * 128;
        int row = s >> 4;
        int c   = s & 15;
        *(float4*)&Qs[row * 68 + c * 4] =
            *(const float4*)&qg[(size_t)(qrow0 + row) * P_DIM + c * 4];
    }

    u64 o2[8][2];                   // packed output accum: dims keyg*4 .. +3
    float m[8], l[8];
#pragma unroll
    for (int i = 0; i < 8; i++) {
        m[i] = -1e30f; l[i] = 0.f;
        o2[i][0] = 0ull; o2[i][1] = 0ull;
    }

    for (int kt = kt0; kt < kt1; kt++) {
        __syncthreads();
        const int krow0 = b * T_SEQ + kt * 64;
#pragma unroll
        for (int it = 0; it < 8; it++) {
            int s   = tid + it * 128;
            int row = s >> 4;
            int c   = s & 15;
            *(float4*)&Ks[row * 68 + c * 4] =
                *(const float4*)&kg[(size_t)(krow0 + row) * P_DIM + c * 4];
            *(float4*)&Vs[row * 68 + c * 4] =
                *(const float4*)&vg[(size_t)(krow0 + row) * P_DIM + c * 4];
        }
        __syncthreads();

        // ---- S = Q K^T, packed over p-pairs ----
        u64 acc2[8][4];
#pragma unroll
        for (int i = 0; i < 8; i++)
#pragma unroll
            for (int j = 0; j < 4; j++) acc2[i][j] = 0ull;

#pragma unroll
        for (int p4 = 0; p4 < 16; p4++) {
            ulonglong2 kv[4];
#pragma unroll
            for (int j = 0; j < 4; j++)
                kv[j] = *(ulonglong2*)&Ks[(keyg + 16 * j) * 68 + p4 * 4];
#pragma unroll
            for (int i = 0; i < 8; i++) {
                ulonglong2 qq = *(ulonglong2*)&Qs[(r0 + i) * 68 + p4 * 4];
#pragma unroll
                for (int j = 0; j < 4; j++) {
                    acc2[i][j] = fma2(qq.x, kv[j].x, acc2[i][j]);
                    acc2[i][j] = fma2(qq.y, kv[j].y, acc2[i][j]);
                }
            }
        }

        // reduce packed pairs -> scalars
        float sv[8][4];
#pragma unroll
        for (int i = 0; i < 8; i++)
#pragma unroll
            for (int j = 0; j < 4; j++) {
                float2 t = unpack2(acc2[i][j]);
                sv[i][j] = t.x + t.y;
            }

        // ---- causal mask (diagonal tile only) ----
        if (kt == qt) {
#pragma unroll
            for (int i = 0; i < 8; i++) {
                int rl = r0 + i;
#pragma unroll
                for (int j = 0; j < 4; j++)
                    if (keyg + 16 * j > rl) sv[i][j] = -1e30f;
            }
        }

        // ---- online softmax ----
#pragma unroll
        for (int i = 0; i < 8; i++) {
            float tmax = fmaxf(fmaxf(sv[i][0], sv[i][1]), fmaxf(sv[i][2], sv[i][3]));
            tmax = fmaxf(tmax, __shfl_xor_sync(0xffffffffu, tmax, 1));
            tmax = fmaxf(tmax, __shfl_xor_sync(0xffffffffu, tmax, 2));
            tmax = fmaxf(tmax, __shfl_xor_sync(0xffffffffu, tmax, 4));
            tmax = fmaxf(tmax, __shfl_xor_sync(0xffffffffu, tmax, 8));

            float mnew  = fmaxf(m[i], tmax);
            float scale = __expf(m[i] - mnew);
            float lsum  = 0.f;
#pragma unroll
            for (int j = 0; j < 4; j++) {
                float p = __expf(sv[i][j] - mnew);
                lsum += p;
                Ps[(r0 + i) * 68 + keyg + 16 * j] = p;
            }
            lsum += __shfl_xor_sync(0xffffffffu, lsum, 1);
            lsum += __shfl_xor_sync(0xffffffffu, lsum, 2);
            lsum += __shfl_xor_sync(0xffffffffu, lsum, 4);
            lsum += __shfl_xor_sync(0xffffffffu, lsum, 8);

            l[i] = l[i] * scale + lsum;
            m[i] = mnew;
            u64 s2 = pack2(scale, scale);
            o2[i][0] = mul2(o2[i][0], s2);
            o2[i][1] = mul2(o2[i][1], s2);
        }
        // Ps rows for this thread's PV are produced within the same warp only
        __syncwarp();

        // ---- O += P V, packed over dim-pairs ----
#pragma unroll
        for (int j4 = 0; j4 < 16; j4++) {
            ulonglong2 vv[4];
#pragma unroll
            for (int j = 0; j < 4; j++)
                vv[j] = *(ulonglong2*)&Vs[(j4 * 4 + j) * 68 + keyg * 4];
#pragma unroll
            for (int i = 0; i < 8; i++) {
                float4 p4 = *(float4*)&Ps[(r0 + i) * 68 + j4 * 4];
                u64 pb;
                pb = pack2(p4.x, p4.x);
                o2[i][0] = fma2(pb, vv[0].x, o2[i][0]);
                o2[i][1] = fma2(pb, vv[0].y, o2[i][1]);
                pb = pack2(p4.y, p4.y);
                o2[i][0] = fma2(pb, vv[1].x, o2[i][0]);
                o2[i][1] = fma2(pb, vv[1].y, o2[i][1]);
                pb = pack2(p4.z, p4.z);
                o2[i][0] = fma2(pb, vv[2].x, o2[i][0]);
                o2[i][1] = fma2(pb, vv[2].y, o2[i][1]);
                pb = pack2(p4.w, p4.w);
                o2[i][0] = fma2(pb, vv[3].x, o2[i][0]);
                o2[i][1] = fma2(pb, vv[3].y, o2[i][1]);
            }
        }
    }

    // ---- write split partials (unnormalized O, and m,l) ----
    float* po  = g_po  + (size_t)sp * M_ROWS * P_DIM;
    float* pml = g_pml + (size_t)sp * M_ROWS * 2;
#pragma unroll
    for (int i = 0; i < 8; i++) {
        int row = qrow0 + r0 + i;
        float2 a = unpack2(o2[i][0]);
        float2 c = unpack2(o2[i][1]);
        float4 ov;
        ov.x = a.x; ov.y = a.y; ov.z = c.x; ov.w = c.y;
        *(float4*)&po[(size_t)row * P_DIM + keyg * 4] = ov;
        if (keyg == 0) {
            pml[row * 2 + 0] = m[i];
            pml[row * 2 + 1] = l[i];
        }
    }
}

// ---------------------------------------------------------------------------
// Combine the NSPLIT partials.
// ---------------------------------------------------------------------------
__global__ __launch_bounds__(256) void combine_kernel(float* __restrict__ out)
{
    int idx = blockIdx.x * 256 + threadIdx.x;
    int row = idx >> 4;
    int c   = idx & 15;

    float m0 = g_pml[row * 2 + 0];
    float l0 = g_pml[row * 2 + 1];
    float m1 = g_pml[(size_t)M_ROWS * 2 + row * 2 + 0];
    float l1 = g_pml[(size_t)M_ROWS * 2 + row * 2 + 1];

    float M  = fmaxf(m0, m1);
    float w0 = __expf(m0 - M);
    float w1 = __expf(m1 - M);
    float inv = 1.0f / (l0 * w0 + l1 * w1);

    float4 a = *(const float4*)&g_po[(size_t)row * P_DIM + c * 4];
    float4 b = *(const float4*)&g_po[(size_t)(M_ROWS + row) * P_DIM + c * 4];
    float4 r;
    r.x = (a.x * w0 + b.x * w1) * inv;
    r.y = (a.y * w0 + b.y * w1) * inv;
    r.z = (a.z * w0 + b.z * w1) * inv;
    r.w = (a.w * w0 + b.w * w1) * inv;
    *(float4*)&out[(size_t)row * P_DIM + c * 4] = r;
}

#define ATTN_SMEM (4 * 64 * 68 * 4)   // 69632 bytes

extern "C" void kernel_launch(void* const* d_in, const int* in_sizes, int n_in,
                              void* d_out, int out_size)
{
    const float* x    = (const float*)d_in[0];   // (4, 4096, 1024)
    const float* W    = (const float*)d_in[1];   // (1024, 192)
    const float* bias = (const float*)d_in[2];   // (192,)
    float* out        = (float*)d_out;           // (4, 4096, 64)

    cudaFuncSetAttribute(attn_kernel,
                         cudaFuncAttributeMaxDynamicSharedMemorySize, ATTN_SMEM);

    qkv_gemm_kernel<<<dim3(M_ROWS / 64, 3), 256>>>(x, W, bias);
    attn_kernel<<<dim3(T_SEQ / 64, B_SZ, NSPLIT), 128, ATTN_SMEM>>>();
    combine_kernel<<<(M_ROWS * 16) / 256, 256>>>(out);
}

// round 17
// speedup vs baseline: 1.8532x; 1.0083x over previous
#include <cuda_runtime.h>
#include <cuda_bf16.h>

#define T_SEQ 4096
#define B_SZ  4
#define D_IN  1024
#define P_DIM 64
#define M_ROWS (B_SZ * T_SEQ)   // 16384
#define NSPLIT 3

typedef unsigned long long u64;

// qkv scratch: [head (q/k/v)][m = b*T + t][p]
__device__ __align__(16) float g_qkv[3u * M_ROWS * P_DIM];
// split partials: unnormalized O, and (m, l) per row per split
__device__ __align__(16) float g_po[NSPLIT * M_ROWS * P_DIM];
__device__ __align__(16) float g_pml[NSPLIT * M_ROWS * 2];
// W transposed: [n (192)][k (1024)]
__device__ __align__(16) float g_wt[192 * D_IN];

// ---------------------------------------------------------------------------
// packed f32x2 helpers (sm_103a FFMA2 path — only reachable via PTX)
// ---------------------------------------------------------------------------
__device__ __forceinline__ u64 fma2(u64 a, u64 b, u64 c) {
    u64 d;
    asm("fma.rn.f32x2 %0, %1, %2, %3;" : "=l"(d) : "l"(a), "l"(b), "l"(c));
    return d;
}
__device__ __forceinline__ u64 mul2(u64 a, u64 b) {
    u64 d;
    asm("mul.rn.f32x2 %0, %1, %2;" : "=l"(d) : "l"(a), "l"(b));
    return d;
}
__device__ __forceinline__ u64 pack2(float x, float y) {
    u64 r;
    asm("mov.b64 %0, {%1, %2};" : "=l"(r) : "f"(x), "f"(y));
    return r;
}
__device__ __forceinline__ float2 unpack2(u64 v) {
    float2 r;
    asm("mov.b64 {%0, %1}, %2;" : "=f"(r.x), "=f"(r.y) : "l"(v));
    return r;
}

// ---------------------------------------------------------------------------
// Prep: transpose W (1024 x 192) -> g_wt (192 x 1024).
// ---------------------------------------------------------------------------
__global__ __launch_bounds__(256) void transpose_w_kernel(const float* __restrict__ W)
{
    int idx = blockIdx.x * 256 + threadIdx.x;   // 192*1024 elements
    int k = idx / 192;
    int n = idx % 192;
    g_wt[(size_t)n * D_IN + k] = W[(size_t)k * 192 + n];
}

// ---------------------------------------------------------------------------
// QKV projection, FFMA2, attention-S-loop structure.
// Block: 64(M) x 64(N = one head), 128 threads:
//   rowg = tid>>4 (8 rows r0..r0+7), keyg = tid&15 (4 cols keyg+16j).
// Both operands k-major rows (x row-major; W pre-transposed), stride 68.
// k-packed fma2 accumulation over 16 K-tiles of 64; pairs reduced at end.
// ---------------------------------------------------------------------------
__global__ __launch_bounds__(128) void qkv_gemm_kernel(
    const float* __restrict__ x,
    const float* __restrict__ bias)
{
    __shared__ float As[64 * 68];
    __shared__ float Bs[64 * 68];

    const int m0   = blockIdx.x * 64;
    const int head = blockIdx.y;
    const int n0   = head * 64;
    const int tid  = threadIdx.x;
    const int rowg = tid >> 4;      // 0..7
    const int keyg = tid & 15;      // 0..15
    const int r0   = rowg * 8;

    u64 acc2[8][4];
#pragma unroll
    for (int i = 0; i < 8; i++)
#pragma unroll
        for (int j = 0; j < 4; j++) acc2[i][j] = 0ull;

    for (int t = 0; t < 16; t++) {
        __syncthreads();
        const int k0 = t * 64;
#pragma unroll
        for (int it = 0; it < 8; it++) {
            int s   = tid + it * 128;
            int row = s >> 4;
            int c   = s & 15;
            *(float4*)&As[row * 68 + c * 4] =
                *(const float4*)&x[(size_t)(m0 + row) * D_IN + k0 + c * 4];
            *(float4*)&Bs[row * 68 + c * 4] =
                *(const float4*)&g_wt[(size_t)(n0 + row) * D_IN + k0 + c * 4];
        }
        __syncthreads();

#pragma unroll
        for (int p4 = 0; p4 < 16; p4++) {
            ulonglong2 kv[4];
#pragma unroll
            for (int j = 0; j < 4; j++)
                kv[j] = *(ulonglong2*)&Bs[(keyg + 16 * j) * 68 + p4 * 4];
#pragma unroll
            for (int i = 0; i < 8; i++) {
                ulonglong2 qq = *(ulonglong2*)&As[(r0 + i) * 68 + p4 * 4];
#pragma unroll
                for (int j = 0; j < 4; j++) {
                    acc2[i][j] = fma2(qq.x, kv[j].x, acc2[i][j]);
                    acc2[i][j] = fma2(qq.y, kv[j].y, acc2[i][j]);
                }
            }
        }
    }

    // epilogue: reduce pairs, add bias, store
    float* outp = g_qkv + (size_t)head * M_ROWS * P_DIM;
#pragma unroll
    for (int i = 0; i < 8; i++) {
        float* orow = outp + (size_t)(m0 + r0 + i) * P_DIM;
#pragma unroll
        for (int j = 0; j < 4; j++) {
            float2 tpair = unpack2(acc2[i][j]);
            int col = keyg + 16 * j;
            orow[col] = tpair.x + tpair.y + bias[n0 + col];
        }
    }
}

// ---------------------------------------------------------------------------
// Flash-style causal attention, register-blocked + key-split + packed FFMA2.
// (R15 structure, NSPLIT=3)
// ---------------------------------------------------------------------------
__global__ __launch_bounds__(128) void attn_kernel()
{
    extern __shared__ float sm[];
    float* Qs = sm;                 // [64][68]
    float* Ks = sm + 4352;          // [64][68]
    float* Vs = sm + 8704;          // [64][68]
    float* Ps = sm + 13056;         // [64][68]

    const int b    = blockIdx.y;
    const int qt   = (int)gridDim.x - 1 - (int)blockIdx.x;  // heavy blocks first
    const int sp   = blockIdx.z;
    const int tid  = threadIdx.x;
    const int rowg = tid >> 4;      // 0..7
    const int keyg = tid & 15;      // 0..15
    const int r0   = rowg * 8;

    const int n   = qt + 1;
    const int kt0 = sp * n / NSPLIT;
    const int kt1 = (sp + 1) * n / NSPLIT;

    const float* qg = g_qkv;
    const float* kg = g_qkv + (size_t)M_ROWS * P_DIM;
    const float* vg = g_qkv + (size_t)2 * M_ROWS * P_DIM;

    const int qrow0 = b * T_SEQ + qt * 64;

#pragma unroll
    for (int it = 0; it < 8; it++) {
        int s   = tid + it * 128;
        int row = s >> 4;
        int c   = s & 15;
        *(float4*)&Qs[row * 68 + c * 4] =
            *(const float4*)&qg[(size_t)(qrow0 + row) * P_DIM + c * 4];
    }

    u64 o2[8][2];
    float m[8], l[8];
#pragma unroll
    for (int i = 0; i < 8; i++) {
        m[i] = -1e30f; l[i] = 0.f;
        o2[i][0] = 0ull; o2[i][1] = 0ull;
    }

    for (int kt = kt0; kt < kt1; kt++) {
        __syncthreads();
        const int krow0 = b * T_SEQ + kt * 64;
#pragma unroll
        for (int it = 0; it < 8; it++) {
            int s   = tid + it * 128;
            int row = s >> 4;
            int c   = s & 15;
            *(float4*)&Ks[row * 68 + c * 4] =
                *(const float4*)&kg[(size_t)(krow0 + row) * P_DIM + c * 4];
            *(float4*)&Vs[row * 68 + c * 4] =
                *(const float4*)&vg[(size_t)(krow0 + row) * P_DIM + c * 4];
        }
        __syncthreads();

        u64 acc2[8][4];
#pragma unroll
        for (int i = 0; i < 8; i++)
#pragma unroll
            for (int j = 0; j < 4; j++) acc2[i][j] = 0ull;

#pragma unroll
        for (int p4 = 0; p4 < 16; p4++) {
            ulonglong2 kv[4];
#pragma unroll
            for (int j = 0; j < 4; j++)
                kv[j] = *(ulonglong2*)&Ks[(keyg + 16 * j) * 68 + p4 * 4];
#pragma unroll
            for (int i = 0; i < 8; i++) {
                ulonglong2 qq = *(ulonglong2*)&Qs[(r0 + i) * 68 + p4 * 4];
#pragma unroll
                for (int j = 0; j < 4; j++) {
                    acc2[i][j] = fma2(qq.x, kv[j].x, acc2[i][j]);
                    acc2[i][j] = fma2(qq.y, kv[j].y, acc2[i][j]);
                }
            }
        }

        float sv[8][4];
#pragma unroll
        for (int i = 0; i < 8; i++)
#pragma unroll
            for (int j = 0; j < 4; j++) {
                float2 t = unpack2(acc2[i][j]);
                sv[i][j] = t.x + t.y;
            }

        if (kt == qt) {
#pragma unroll
            for (int i = 0; i < 8; i++) {
                int rl = r0 + i;
#pragma unroll
                for (int j = 0; j < 4; j++)
                    if (keyg + 16 * j > rl) sv[i][j] = -1e30f;
            }
        }

#pragma unroll
        for (int i = 0; i < 8; i++) {
            float tmax = fmaxf(fmaxf(sv[i][0], sv[i][1]), fmaxf(sv[i][2], sv[i][3]));
            tmax = fmaxf(tmax, __shfl_xor_sync(0xffffffffu, tmax, 1));
            tmax = fmaxf(tmax, __shfl_xor_sync(0xffffffffu, tmax, 2));
            tmax = fmaxf(tmax, __shfl_xor_sync(0xffffffffu, tmax, 4));
            tmax = fmaxf(tmax, __shfl_xor_sync(0xffffffffu, tmax, 8));

            float mnew  = fmaxf(m[i], tmax);
            float scale = __expf(m[i] - mnew);
            float lsum  = 0.f;
#pragma unroll
            for (int j = 0; j < 4; j++) {
                float p = __expf(sv[i][j] - mnew);
                lsum += p;
                Ps[(r0 + i) * 68 + keyg + 16 * j] = p;
            }
            lsum += __shfl_xor_sync(0xffffffffu, lsum, 1);
            lsum += __shfl_xor_sync(0xffffffffu, lsum, 2);
            lsum += __shfl_xor_sync(0xffffffffu, lsum, 4);
            lsum += __shfl_xor_sync(0xffffffffu, lsum, 8);

            l[i] = l[i] * scale + lsum;
            m[i] = mnew;
            u64 s2 = pack2(scale, scale);
            o2[i][0] = mul2(o2[i][0], s2);
            o2[i][1] = mul2(o2[i][1], s2);
        }
        __syncwarp();

#pragma unroll
        for (int j4 = 0; j4 < 16; j4++) {
            ulonglong2 vv[4];
#pragma unroll
            for (int j = 0; j < 4; j++)
                vv[j] = *(ulonglong2*)&Vs[(j4 * 4 + j) * 68 + keyg * 4];
#pragma unroll
            for (int i = 0; i < 8; i++) {
                float4 p4 = *(float4*)&Ps[(r0 + i) * 68 + j4 * 4];
                u64 pb;
                pb = pack2(p4.x, p4.x);
                o2[i][0] = fma2(pb, vv[0].x, o2[i][0]);
                o2[i][1] = fma2(pb, vv[0].y, o2[i][1]);
                pb = pack2(p4.y, p4.y);
                o2[i][0] = fma2(pb, vv[1].x, o2[i][0]);
                o2[i][1] = fma2(pb, vv[1].y, o2[i][1]);
                pb = pack2(p4.z, p4.z);
                o2[i][0] = fma2(pb, vv[2].x, o2[i][0]);
                o2[i][1] = fma2(pb, vv[2].y, o2[i][1]);
                pb = pack2(p4.w, p4.w);
                o2[i][0] = fma2(pb, vv[3].x, o2[i][0]);
                o2[i][1] = fma2(pb, vv[3].y, o2[i][1]);
            }
        }
    }

    float* po  = g_po  + (size_t)sp * M_ROWS * P_DIM;
    float* pml = g_pml + (size_t)sp * M_ROWS * 2;
#pragma unroll
    for (int i = 0; i < 8; i++) {
        int row = qrow0 + r0 + i;
        float2 a = unpack2(o2[i][0]);
        float2 c = unpack2(o2[i][1]);
        float4 ov;
        ov.x = a.x; ov.y = a.y; ov.z = c.x; ov.w = c.y;
        *(float4*)&po[(size_t)row * P_DIM + keyg * 4] = ov;
        if (keyg == 0) {
            pml[row * 2 + 0] = m[i];
            pml[row * 2 + 1] = l[i];
        }
    }
}

// ---------------------------------------------------------------------------
// Combine the NSPLIT partials: O = sum_s(o_s e^{m_s-M}) / sum_s(l_s e^{m_s-M}).
// Empty splits carry (m=-1e30, l=0) -> weight exp(-huge)=0, harmless.
// ---------------------------------------------------------------------------
__global__ __launch_bounds__(256) void combine_kernel(float* __restrict__ out)
{
    int idx = blockIdx.x * 256 + threadIdx.x;
    int row = idx >> 4;
    int c   = idx & 15;

    float ms[NSPLIT], ls[NSPLIT];
    float M = -1e30f;
#pragma unroll
    for (int s = 0; s < NSPLIT; s++) {
        ms[s] = g_pml[(size_t)s * M_ROWS * 2 + row * 2 + 0];
        ls[s] = g_pml[(size_t)s * M_ROWS * 2 + row * 2 + 1];
        M = fmaxf(M, ms[s]);
    }
    float denom = 0.f;
    float w[NSPLIT];
#pragma unroll
    for (int s = 0; s < NSPLIT; s++) {
        w[s] = __expf(ms[s] - M);
        denom += ls[s] * w[s];
    }
    float inv = 1.0f / denom;

    float4 r = make_float4(0.f, 0.f, 0.f, 0.f);
#pragma unroll
    for (int s = 0; s < NSPLIT; s++) {
        float4 a = *(const float4*)&g_po[(size_t)(s * M_ROWS + row) * P_DIM + c * 4];
        r.x += a.x * w[s];
        r.y += a.y * w[s];
        r.z += a.z * w[s];
        r.w += a.w * w[s];
    }
    r.x *= inv; r.y *= inv; r.z *= inv; r.w *= inv;
    *(float4*)&out[(size_t)row * P_DIM + c * 4] = r;
}

#define ATTN_SMEM (4 * 64 * 68 * 4)   // 69632 bytes

extern "C" void kernel_launch(void* const* d_in, const int* in_sizes, int n_in,
                              void* d_out, int out_size)
{
    const float* x    = (const float*)d_in[0];   // (4, 4096, 1024)
    const float* W    = (const float*)d_in[1];   // (1024, 192)
    const float* bias = (const float*)d_in[2];   // (192,)
    float* out        = (float*)d_out;           // (4, 4096, 64)

    cudaFuncSetAttribute(attn_kernel,
                         cudaFuncAttributeMaxDynamicSharedMemorySize, ATTN_SMEM);

    transpose_w_kernel<<<(192 * D_IN) / 256, 256>>>(W);
    qkv_gemm_kernel<<<dim3(M_ROWS / 64, 3), 128>>>(x, bias);
    attn_kernel<<<dim3(T_SEQ / 64, B_SZ, NSPLIT), 128, ATTN_SMEM>>>();
    combine_kernel<<<(M_ROWS * 16) / 256, 256>>>(out);
}